// round 1
// baseline (speedup 1.0000x reference)
#include <cuda_runtime.h>
#include <cstddef>

// SpecialFlatten: out[b, i*R*2 + j*2 + p] = x[b, j, 2i+p]
// == batched transpose of float2 matrices: in2 [B, R, CP] -> out2 [B, CP, R]
// with B=32, R=2048, C=512, CP=C/2=256.

namespace {
constexpr int B  = 32;
constexpr int R  = 2048;
constexpr int CP = 256;      // C/2, float2 elements per input row
constexpr int TILE  = 32;
constexpr int BROWS = 8;
}

__global__ __launch_bounds__(TILE * BROWS)
void special_flatten_transpose(const float2* __restrict__ in,
                               float2* __restrict__ out) {
    __shared__ float2 tile[TILE][TILE + 1];

    const int b = blockIdx.z;
    const float2* __restrict__ inb  = in  + (size_t)b * R * CP;
    float2* __restrict__       outb = out + (size_t)b * R * CP;

    // Input coordinates: x along CP (contiguous), y along R
    const int xi = blockIdx.x * TILE + threadIdx.x;
    const int yi = blockIdx.y * TILE + threadIdx.y;

#pragma unroll
    for (int k = 0; k < TILE; k += BROWS) {
        tile[threadIdx.y + k][threadIdx.x] = inb[(size_t)(yi + k) * CP + xi];
    }

    __syncthreads();

    // Output coordinates: x along R (contiguous), y along CP
    const int xo = blockIdx.y * TILE + threadIdx.x;
    const int yo = blockIdx.x * TILE + threadIdx.y;

#pragma unroll
    for (int k = 0; k < TILE; k += BROWS) {
        outb[(size_t)(yo + k) * R + xo] = tile[threadIdx.x][threadIdx.y + k];
    }
}

extern "C" void kernel_launch(void* const* d_in, const int* in_sizes, int n_in,
                              void* d_out, int out_size) {
    const float2* in  = (const float2*)d_in[0];
    float2*       out = (float2*)d_out;

    dim3 block(TILE, BROWS, 1);
    dim3 grid(CP / TILE, R / TILE, B);   // (8, 64, 32)
    special_flatten_transpose<<<grid, block>>>(in, out);
}